// round 10
// baseline (speedup 1.0000x reference)
#include <cuda_runtime.h>
#include <cuda_bf16.h>

// Problem constants
#define B_DIM 128
#define L_DIM 1024
#define D_DIM 128
#define DVF   32          // D/4 float4 groups (full row)
#define DT    8           // float4 groups per D-tile (D split 4 ways)
#define TSTART 128        // output start positions per L tile
#define NPOS  159         // TSTART + 31 halo positions (mask)
#define NS4   156         // sliding-4-sum rows: TSTART + 28
#define NTHREADS 512
#define GROUP 256         // threads per role group
#define GRID  592         // 148 SMs x 4 CTAs, single persistent wave
#define NTILES_TOTAL 4096 // 8 L-tiles x 4 D-tiles x 128 batches

// Output row offsets for window sizes 4, 8, 16, 32
#define OFF4  0
#define OFF8  1021
#define OFF16 2038
#define OFF32 3047
#define ROWS  4040

// Shared memory (floats):
//   s4buf : 2 x NS4*DT float4 = 9984 floats
//   inv   : 2 x 512 floats    = 1024
//   msk   : 2 x 160 ints      = 320
#define S4_F4       (NS4 * DT)
#define SMEM_FLOATS (2 * S4_F4 * 4 + 2 * 512 + 2 * 160)
#define SMEM_BYTES  (SMEM_FLOATS * 4)

__device__ __forceinline__ float4 add4(float4 a, float4 b) {
    return make_float4(a.x + b.x, a.y + b.y, a.z + b.z, a.w + b.w);
}
__device__ __forceinline__ float4 scl4(float4 a, float s) {
    return make_float4(a.x * s, a.y * s, a.z * s, a.w * s);
}
__device__ __forceinline__ void decode_tile(int t, int& b, int& dbase, int& s0) {
    b     = t & 127;
    dbase = ((t >> 7) & 3) * DT;
    s0    = (t >> 9) * TSTART;
}

extern __shared__ float smem_raw[];

__global__ __launch_bounds__(NTHREADS, 4)
void msse_kernel(const float* __restrict__ x,
                 const int* __restrict__ mask,
                 float* __restrict__ out)
{
    const int cta = blockIdx.x;
    const int tid = threadIdx.x;
    const bool isA = (tid < GROUP);       // warps 0-7: producer (s4 build)
    const int  g   = isA ? tid : tid - GROUP;

    float4* s4buf  = reinterpret_cast<float4*>(smem_raw);          // [2][S4_F4]
    float*  invbuf = reinterpret_cast<float*>(s4buf + 2 * S4_F4);  // [2][512]
    int*    mskbuf = reinterpret_cast<int*>(invbuf + 2 * 512);     // [2][160]

    const int NT = (NTILES_TOTAL - 1 - cta) / GRID + 1;  // tiles for this CTA

    // ---- prologue: group A loads mask for tile 0 into slot 0 ----
    if (isA) {
        int b, dbase, s0;
        decode_tile(cta, b, dbase, s0);
        const int* mrow = mask + (size_t)b * L_DIM;
        for (int p = g; p < NPOS; p += GROUP) {
            int gg = s0 + p;
            mskbuf[p] = (gg < L_DIM) ? mrow[gg] : 0;
        }
        if (g < 1) mskbuf[NPOS] = 0;  // pad
    }
    __syncthreads();

    for (int it = 0; it <= NT; ++it) {
        if (isA && it < NT) {
            // ================= PRODUCER: build s4 + inv for tile `it` ======
            const int t = cta + it * GRID;
            int b, dbase, s0;
            decode_tile(t, b, dbase, s0);
            const int slot = it & 1;
            int*    msk = mskbuf + slot * 160;
            float4* s4  = s4buf + slot * S4_F4;
            float*  inv = invbuf + slot * 512;

            const float4* xrow = reinterpret_cast<const float4*>(
                x + (size_t)b * L_DIM * D_DIM);
            const float4 fz = make_float4(0.f, 0.f, 0.f, 0.f);

            for (int i = g; i < NS4 * DT; i += GROUP) {
                int p = i >> 3;
                int q = i & 7;
                const float4* base = xrow + (size_t)(s0 + p) * DVF + dbase + q;
                float4 acc = fz;
                #pragma unroll
                for (int k = 0; k < 4; k++) {
                    if (msk[p + k]) acc = add4(acc, __ldg(base + k * DVF));
                }
                s4[i] = acc;
            }

            if (g < TSTART) {
                int j = g;
                int c = 0;
                #pragma unroll
                for (int k = 0; k < 4; k++)  c += msk[j + k];
                int c4 = c;
                #pragma unroll
                for (int k = 4; k < 8; k++)  c += msk[j + k];
                int c8 = c;
                #pragma unroll
                for (int k = 8; k < 16; k++) c += msk[j + k];
                int c16 = c;
                #pragma unroll
                for (int k = 16; k < 32; k++) c += msk[j + k];
                int c32 = c;
                inv[0 * TSTART + j] = 1.0f / (float)(c4  > 1 ? c4  : 1);
                inv[1 * TSTART + j] = 1.0f / (float)(c8  > 1 ? c8  : 1);
                inv[2 * TSTART + j] = 1.0f / (float)(c16 > 1 ? c16 : 1);
                inv[3 * TSTART + j] = 1.0f / (float)(c32 > 1 ? c32 : 1);
            }

            // prefetch mask for tile it+1 into the other slot
            if (it + 1 < NT) {
                const int t2 = cta + (it + 1) * GRID;
                int b2, db2, s02;
                decode_tile(t2, b2, db2, s02);
                const int* mrow2 = mask + (size_t)b2 * L_DIM;
                int* msk2 = mskbuf + ((it + 1) & 1) * 160;
                for (int p = g; p < NPOS; p += GROUP) {
                    int gg = s02 + p;
                    msk2[p] = (gg < L_DIM) ? mrow2[gg] : 0;
                }
            }
        } else if (!isA && it >= 1) {
            // ================= CONSUMER: phase 3 for tile `it-1` ===========
            const int t = cta + (it - 1) * GRID;
            int b, dbase, s0;
            decode_tile(t, b, dbase, s0);
            const int slot = (it - 1) & 1;
            const float4* s4  = s4buf + slot * S4_F4;
            const float*  inv = invbuf + slot * 512;

            float4* outb = reinterpret_cast<float4*>(out + (size_t)b * ROWS * D_DIM);

            #pragma unroll
            for (int half = 0; half < 2; half++) {
                const int tv  = g + half * GROUP;   // virtual tid 0..511
                const int q   = tv & 7;
                const int idx = tv >> 3;
                const int jm  = idx & 3;
                const int kk  = idx >> 2;
                const int j0  = jm + 8 * kk;
                const int j1  = j0 + 4;
                const int gi0 = s0 + j0;
                const int gi1 = s0 + j1;
                const int oq  = dbase + q;
                const float4* sp = s4 + j0 * DT + q;

                float4 a    = sp[0];
                float4 accA = a;
                if (gi0 <= L_DIM - 4)
                    __stcs(&outb[(OFF4 + gi0) * DVF + oq], scl4(a, inv[0 * TSTART + j0]));
                a = sp[4 * DT];
                float4 accB = a;
                if (gi1 <= L_DIM - 4)
                    __stcs(&outb[(OFF4 + gi1) * DVF + oq], scl4(a, inv[0 * TSTART + j1]));
                accA = add4(accA, a);
                if (gi0 <= L_DIM - 8)
                    __stcs(&outb[(OFF8 + gi0) * DVF + oq], scl4(accA, inv[1 * TSTART + j0]));
                a = sp[8 * DT];
                accB = add4(accB, a);
                if (gi1 <= L_DIM - 8)
                    __stcs(&outb[(OFF8 + gi1) * DVF + oq], scl4(accB, inv[1 * TSTART + j1]));
                accA = add4(accA, a);
                a = sp[12 * DT];
                accA = add4(accA, a);
                if (gi0 <= L_DIM - 16)
                    __stcs(&outb[(OFF16 + gi0) * DVF + oq], scl4(accA, inv[2 * TSTART + j0]));
                accB = add4(accB, a);
                a = sp[16 * DT];
                accB = add4(accB, a);
                if (gi1 <= L_DIM - 16)
                    __stcs(&outb[(OFF16 + gi1) * DVF + oq], scl4(accB, inv[2 * TSTART + j1]));
                accA = add4(accA, a);
                a = sp[20 * DT];
                accA = add4(accA, a);
                accB = add4(accB, a);
                a = sp[24 * DT];
                accA = add4(accA, a);
                accB = add4(accB, a);
                a = sp[28 * DT];
                accA = add4(accA, a);
                if (gi0 <= L_DIM - 32)
                    __stcs(&outb[(OFF32 + gi0) * DVF + oq], scl4(accA, inv[3 * TSTART + j0]));
                accB = add4(accB, a);
                a = sp[32 * DT];
                accB = add4(accB, a);
                if (gi1 <= L_DIM - 32)
                    __stcs(&outb[(OFF32 + gi1) * DVF + oq], scl4(accB, inv[3 * TSTART + j1]));
            }
        }
        __syncthreads();   // s4[nxt]/msk[nxt] ready; consumer done with s4[cur]
    }
}

extern "C" void kernel_launch(void* const* d_in, const int* in_sizes, int n_in,
                              void* d_out, int out_size)
{
    const float* x    = (const float*)d_in[0];
    const int*   mask = (const int*)d_in[1];
    float*       out  = (float*)d_out;

    cudaFuncSetAttribute(msse_kernel,
                         cudaFuncAttributeMaxDynamicSharedMemorySize, SMEM_BYTES);

    msse_kernel<<<GRID, NTHREADS, SMEM_BYTES>>>(x, mask, out);
}